// round 6
// baseline (speedup 1.0000x reference)
#include <cuda_runtime.h>
#include <math.h>

#define HH 512
#define WW 512
#define NB 8
#define NIMG 16
#define NBLK 256
#define NTHR 512
#define NW 16            // warps per block
#define FULL 0xffffffffu

// packed thresholded masks: [image][row][16 words of 32 cols] = 512 KB
__device__ unsigned int g_mbits[NIMG][HH][16];
// per-(image, block-slice) nonempty flags (written unconditionally -> replay safe)
__device__ int g_anyp[NIMG][16];
// running max dt^2 per EDT-image. Reset by finalizer each replay.
__device__ unsigned int g_hmax[NIMG];
// monotonic generation barriers (grow across replays)
__device__ unsigned int g_bar1 = 0;
__device__ unsigned int g_bar2 = 0;

// nearest set-bit horizontal distance in a 512-bit packed row (clamped 1024)
__device__ __forceinline__ int nearest_dj(const unsigned int* __restrict__ rb, int j) {
    int jw = j >> 5, jb = j & 31;
    unsigned wj = rb[jw];
    int dright = 1 << 20;
    unsigned hi = wj >> jb;
    if (hi) dright = __ffs(hi) - 1;
    else {
        #pragma unroll 4
        for (int w = jw + 1; w < 16; w++) {
            unsigned x = rb[w];
            if (x) { dright = (w << 5) + __ffs(x) - 1 - j; break; }
        }
    }
    int dleft = 1 << 20;
    unsigned lo = jb ? (wj & ((1u << jb) - 1u)) : 0u;
    if (lo) dleft = jb - (31 - __clz(lo));
    else {
        #pragma unroll 4
        for (int w = jw - 1; w >= 0; w--) {
            if ((j - ((w << 5) + 31)) >= dright) break;   // cannot beat right side
            unsigned x = rb[w];
            if (x) { dleft = j - ((w << 5) + 31 - __clz(x)); break; }
        }
    }
    return min(min(dright, dleft), 1024);
}

// exact squared distance for a rare "leftover" pixel (no true in its 3x3)
__device__ __forceinline__ int exact_d2(int im, int row, int j) {
    int best2 = 1 << 19;                 // > 511^2 + 511^2
    for (int dr = 0; dr < HH; dr++) {
        int dr2 = dr * dr;
        if (dr2 >= best2) break;         // exact termination
        int r = row - dr;
        if (r >= 0) {
            int dj = nearest_dj(g_mbits[im][r], j);
            best2 = min(best2, dr2 + dj * dj);
        }
        if (dr) {
            r = row + dr;
            if (r < HH) {
                int dj = nearest_dj(g_mbits[im][r], j);
                best2 = min(best2, dr2 + dj * dj);
            }
        }
    }
    return best2;
}

// pack 16 threshold bits from 4 float4 loads (frag bit p <-> col lane*16+p)
__device__ __forceinline__ unsigned pack16(const float4* __restrict__ rp4, int lane) {
    float4 a = rp4[lane * 4 + 0];
    float4 b = rp4[lane * 4 + 1];
    float4 c = rp4[lane * 4 + 2];
    float4 d = rp4[lane * 4 + 3];
    unsigned f = 0u;
    f |= (a.x > 0.5f ? 1u : 0u) << 0;  f |= (a.y > 0.5f ? 1u : 0u) << 1;
    f |= (a.z > 0.5f ? 1u : 0u) << 2;  f |= (a.w > 0.5f ? 1u : 0u) << 3;
    f |= (b.x > 0.5f ? 1u : 0u) << 4;  f |= (b.y > 0.5f ? 1u : 0u) << 5;
    f |= (b.z > 0.5f ? 1u : 0u) << 6;  f |= (b.w > 0.5f ? 1u : 0u) << 7;
    f |= (c.x > 0.5f ? 1u : 0u) << 8;  f |= (c.y > 0.5f ? 1u : 0u) << 9;
    f |= (c.z > 0.5f ? 1u : 0u) << 10; f |= (c.w > 0.5f ? 1u : 0u) << 11;
    f |= (d.x > 0.5f ? 1u : 0u) << 12; f |= (d.y > 0.5f ? 1u : 0u) << 13;
    f |= (d.z > 0.5f ? 1u : 0u) << 14; f |= (d.w > 0.5f ? 1u : 0u) << 15;
    return f;
}

__global__ __launch_bounds__(NTHR, 2)
void hausdorff_fused(const float* __restrict__ inA,
                     const float* __restrict__ inB,
                     float* __restrict__ out) {
    __shared__ int s_red[NW];
    const int t    = threadIdx.x;
    const int w    = t >> 5;
    const int lane = t & 31;
    const int blk  = blockIdx.x;
    const int gw   = blk * NW + w;        // 0..4095
    const int im   = gw >> 8;             // 256 warp-units per image
    const int pair = gw & 255;            // 2 rows per warp
    const int row0 = pair * 2;

    // ------- Phase 1: threshold + bit-pack, high-MLP vector loads -----------
    {
        const int b = im & 7;
        const float* src = ((im < NB) ? inA : inB) + (size_t)b * HH * WW;
        // two rows, 8 independent LDG.128 per thread total
        unsigned f0 = pack16((const float4*)(src + (size_t)row0 * WW), lane);
        unsigned f1 = pack16((const float4*)(src + (size_t)(row0 + 1) * WW), lane);

        int widx = (lane & 15) * 2;
        unsigned w0 = __shfl_sync(FULL, f0, widx) | (__shfl_sync(FULL, f0, widx + 1) << 16);
        unsigned w1 = __shfl_sync(FULL, f1, widx) | (__shfl_sync(FULL, f1, widx + 1) << 16);
        if (lane < 16) {
            g_mbits[im][row0][lane]     = w0;
            g_mbits[im][row0 + 1][lane] = w1;
        }
        int anyb = __syncthreads_or((f0 | f1) != 0u);
        if (t == 0) g_anyp[blk >> 4][blk & 15] = anyb;   // im == blk>>4
    }

    // ------- grid barrier (all 256 blocks resident at occupancy 2) ----------
    {
        __syncthreads();
        if (t == 0) {
            __threadfence();
            unsigned old = atomicAdd(&g_bar1, 1u);
            unsigned target = (old / NBLK + 1u) * NBLK;
            while (*(volatile unsigned int*)&g_bar1 < target) { }
            __threadfence();
        }
        __syncthreads();
    }

    // ------- Phase 2: tiered exact Hausdorff max ----------------------------
    {
        const int half = lane >> 4;           // which of the 2 rows
        const int ln   = lane & 15;           // word index within row
        const int row  = row0 + half;
        const int oim  = im ^ 8;

        unsigned C = g_mbits[im][row][ln];
        unsigned U = (row > 0)      ? g_mbits[im][row - 1][ln] : 0u;
        unsigned D = (row < HH - 1) ? g_mbits[im][row + 1][ln] : 0u;
        unsigned G = g_mbits[oim][row][ln];

        unsigned Cm = __shfl_sync(FULL, C, (lane + 31) & 31);
        unsigned Cp = __shfl_sync(FULL, C, (lane + 1) & 31);
        unsigned Um = __shfl_sync(FULL, U, (lane + 31) & 31);
        unsigned Up = __shfl_sync(FULL, U, (lane + 1) & 31);
        unsigned Dm = __shfl_sync(FULL, D, (lane + 31) & 31);
        unsigned Dp = __shfl_sync(FULL, D, (lane + 1) & 31);
        if (ln == 0)  { Cm = 0u; Um = 0u; Dm = 0u; }
        if (ln == 15) { Cp = 0u; Up = 0u; Dp = 0u; }

        unsigned sC = ((C << 1) | (Cm >> 31)) | ((C >> 1) | (Cp << 31));
        unsigned sU = ((U << 1) | (Um >> 31)) | ((U >> 1) | (Up << 31));
        unsigned sD = ((D << 1) | (Dm >> 31)) | ((D >> 1) | (Dp << 31));

        unsigned e1 = sC | U | D;             // dist^2 == 1 (if not 0)
        unsigned e2 = sU | sD;                // dist^2 == 2 (if not 0/1)
        unsigned leftover = G & ~(C | e1 | e2);

        int v = (G & e2 & ~(e1 | C)) ? 2 : ((G & e1 & ~C) ? 1 : 0);

        int j0 = ln * 32;
        while (leftover) {
            int bbit = __ffs(leftover) - 1;
            leftover &= leftover - 1u;
            v = max(v, exact_d2(im, row, j0 + bbit));
        }

        #pragma unroll
        for (int o = 16; o > 0; o >>= 1)
            v = max(v, __shfl_down_sync(FULL, v, o));
        if (lane == 0) s_red[w] = v;
        __syncthreads();
        if (t == 0) {
            int m = s_red[0];
            #pragma unroll
            for (int k = 1; k < NW; k++) m = max(m, s_red[k]);
            atomicMax(&g_hmax[blk >> 4], (unsigned)m);
        }
    }

    // ------- completion: block 0 finalizes ----------------------------------
    __syncthreads();
    __shared__ unsigned s_old;
    if (t == 0) {
        __threadfence();
        s_old = atomicAdd(&g_bar2, 1u);
    }
    if (blk != 0) return;
    __syncthreads();
    if (t == 0) {
        unsigned target = (s_old / NBLK + 1u) * NBLK;
        while (*(volatile unsigned int*)&g_bar2 < target) { }
        __threadfence();
    }
    __syncthreads();

    if (t < 32) {
        float term = 0.0f;
        unsigned h2u = 0u;
        int anyA = 0, anyB = 0;
        if (t < NB) {
            h2u = max(g_hmax[t], g_hmax[t + 8]);
            #pragma unroll
            for (int k = 0; k < 16; k++) {
                anyA |= g_anyp[t][k];
                anyB |= g_anyp[t + 8][k];
            }
        }
        __syncwarp();
        if (t < NIMG) g_hmax[t] = 0u;        // reset for next replay
        if (t < NB) {
            bool empty = !(anyA && anyB);
            float hd = sqrtf((float)h2u);
            term = empty ? 1.0f : (1.0f - 1.0f / (1.0f + hd));
        }
        #pragma unroll
        for (int o = 16; o > 0; o >>= 1)
            term += __shfl_down_sync(FULL, term, o);
        if (t == 0) out[0] = term / (float)NB;
    }
}

extern "C" void kernel_launch(void* const* d_in, const int* in_sizes, int n_in,
                              void* d_out, int out_size) {
    const float* inputs  = (const float*)d_in[0];
    const float* targets = (const float*)d_in[1];
    float* out = (float*)d_out;
    hausdorff_fused<<<NBLK, NTHR>>>(inputs, targets, out);
}

// round 7
// speedup vs baseline: 1.1611x; 1.1611x over previous
#include <cuda_runtime.h>
#include <math.h>

#define HH 512
#define WW 512
#define NB 8
#define NIMG 16
#define NBLK 256
#define NTHR 512
#define NW 16            // warps per block
#define FULL 0xffffffffu

// packed thresholded masks: [image][row][16 words of 32 cols] = 512 KB
__device__ unsigned int g_mbits[NIMG][HH][16];
// per-(image, block-slice) nonempty flags (written unconditionally -> replay safe)
__device__ int g_anyp[NIMG][16];
// running max dt^2 per EDT-image. Reset by finalizer each replay.
__device__ unsigned int g_hmax[NIMG];
// monotonic generation barriers (grow across replays)
__device__ unsigned int g_bar1 = 0;
__device__ unsigned int g_bar2 = 0;

// nearest set-bit horizontal distance in a 512-bit packed row (clamped 1024)
__device__ __forceinline__ int nearest_dj(const unsigned int* __restrict__ rb, int j) {
    int jw = j >> 5, jb = j & 31;
    unsigned wj = rb[jw];
    int dright = 1 << 20;
    unsigned hi = wj >> jb;
    if (hi) dright = __ffs(hi) - 1;
    else {
        #pragma unroll 4
        for (int w = jw + 1; w < 16; w++) {
            unsigned x = rb[w];
            if (x) { dright = (w << 5) + __ffs(x) - 1 - j; break; }
        }
    }
    int dleft = 1 << 20;
    unsigned lo = jb ? (wj & ((1u << jb) - 1u)) : 0u;
    if (lo) dleft = jb - (31 - __clz(lo));
    else {
        #pragma unroll 4
        for (int w = jw - 1; w >= 0; w--) {
            if ((j - ((w << 5) + 31)) >= dright) break;
            unsigned x = rb[w];
            if (x) { dleft = j - ((w << 5) + 31 - __clz(x)); break; }
        }
    }
    return min(min(dright, dleft), 1024);
}

// exact squared distance for an (astronomically rare) pixel with empty 5x5
__device__ __forceinline__ int exact_d2(int im, int row, int j) {
    int best2 = 1 << 19;
    for (int dr = 0; dr < HH; dr++) {
        int dr2 = dr * dr;
        if (dr2 >= best2) break;
        int r = row - dr;
        if (r >= 0) {
            int dj = nearest_dj(g_mbits[im][r], j);
            best2 = min(best2, dr2 + dj * dj);
        }
        if (dr) {
            r = row + dr;
            if (r < HH) {
                int dj = nearest_dj(g_mbits[im][r], j);
                best2 = min(best2, dr2 + dj * dj);
            }
        }
    }
    return best2;
}

// pack 16 threshold bits from 4 float4 loads (frag bit p <-> col lane*16+p)
__device__ __forceinline__ unsigned pack16(const float4* __restrict__ rp4, int lane) {
    float4 a = rp4[lane * 4 + 0];
    float4 b = rp4[lane * 4 + 1];
    float4 c = rp4[lane * 4 + 2];
    float4 d = rp4[lane * 4 + 3];
    unsigned f = 0u;
    f |= (a.x > 0.5f ? 1u : 0u) << 0;  f |= (a.y > 0.5f ? 1u : 0u) << 1;
    f |= (a.z > 0.5f ? 1u : 0u) << 2;  f |= (a.w > 0.5f ? 1u : 0u) << 3;
    f |= (b.x > 0.5f ? 1u : 0u) << 4;  f |= (b.y > 0.5f ? 1u : 0u) << 5;
    f |= (b.z > 0.5f ? 1u : 0u) << 6;  f |= (b.w > 0.5f ? 1u : 0u) << 7;
    f |= (c.x > 0.5f ? 1u : 0u) << 8;  f |= (c.y > 0.5f ? 1u : 0u) << 9;
    f |= (c.z > 0.5f ? 1u : 0u) << 10; f |= (c.w > 0.5f ? 1u : 0u) << 11;
    f |= (d.x > 0.5f ? 1u : 0u) << 12; f |= (d.y > 0.5f ? 1u : 0u) << 13;
    f |= (d.z > 0.5f ? 1u : 0u) << 14; f |= (d.w > 0.5f ? 1u : 0u) << 15;
    return f;
}

// OR of left/right shifts by 1 / by 2 with cross-word carries
__device__ __forceinline__ unsigned sh1(unsigned x, unsigned xm, unsigned xp) {
    return ((x << 1) | (xm >> 31)) | ((x >> 1) | (xp << 31));
}
__device__ __forceinline__ unsigned sh2(unsigned x, unsigned xm, unsigned xp) {
    return ((x << 2) | (xm >> 30)) | ((x >> 2) | (xp << 30));
}

__global__ __launch_bounds__(NTHR, 2)
void hausdorff_fused(const float* __restrict__ inA,
                     const float* __restrict__ inB,
                     float* __restrict__ out) {
    __shared__ int s_red[NW];
    const int t    = threadIdx.x;
    const int w    = t >> 5;
    const int lane = t & 31;
    const int blk  = blockIdx.x;
    const int gw   = blk * NW + w;        // 0..4095
    const int im   = gw >> 8;             // 256 warp-units per image
    const int pair = gw & 255;
    const int row0 = pair * 2;

    // ------- Phase 1: threshold + bit-pack ----------------------------------
    {
        const int b = im & 7;
        const float* src = ((im < NB) ? inA : inB) + (size_t)b * HH * WW;
        unsigned f0 = pack16((const float4*)(src + (size_t)row0 * WW), lane);
        unsigned f1 = pack16((const float4*)(src + (size_t)(row0 + 1) * WW), lane);

        int widx = (lane & 15) * 2;
        unsigned w0 = __shfl_sync(FULL, f0, widx) | (__shfl_sync(FULL, f0, widx + 1) << 16);
        unsigned w1 = __shfl_sync(FULL, f1, widx) | (__shfl_sync(FULL, f1, widx + 1) << 16);
        if (lane < 16) {
            g_mbits[im][row0][lane]     = w0;
            g_mbits[im][row0 + 1][lane] = w1;
        }
        int anyb = __syncthreads_or((f0 | f1) != 0u);
        if (t == 0) g_anyp[blk >> 4][blk & 15] = anyb;
    }

    // ------- grid barrier ---------------------------------------------------
    {
        __syncthreads();
        if (t == 0) {
            __threadfence();
            unsigned old = atomicAdd(&g_bar1, 1u);
            unsigned target = (old / NBLK + 1u) * NBLK;
            while (*(volatile unsigned int*)&g_bar1 < target) { }
            __threadfence();
        }
        __syncthreads();
    }

    // ------- Phase 2: 5x5 tiered exact Hausdorff max ------------------------
    {
        const int half = lane >> 4;
        const int ln   = lane & 15;
        const int row  = row0 + half;
        const int oim  = im ^ 8;

        unsigned C  = g_mbits[im][row][ln];
        unsigned U1 = (row > 0)      ? g_mbits[im][row - 1][ln] : 0u;
        unsigned D1 = (row < HH - 1) ? g_mbits[im][row + 1][ln] : 0u;
        unsigned U2 = (row > 1)      ? g_mbits[im][row - 2][ln] : 0u;
        unsigned D2 = (row < HH - 2) ? g_mbits[im][row + 2][ln] : 0u;
        unsigned G  = g_mbits[oim][row][ln];

        // neighbor words (within the same row's 16-word strip)
        unsigned Cm  = __shfl_sync(FULL, C,  (lane + 31) & 31);
        unsigned Cp  = __shfl_sync(FULL, C,  (lane + 1) & 31);
        unsigned U1m = __shfl_sync(FULL, U1, (lane + 31) & 31);
        unsigned U1p = __shfl_sync(FULL, U1, (lane + 1) & 31);
        unsigned D1m = __shfl_sync(FULL, D1, (lane + 31) & 31);
        unsigned D1p = __shfl_sync(FULL, D1, (lane + 1) & 31);
        unsigned U2m = __shfl_sync(FULL, U2, (lane + 31) & 31);
        unsigned U2p = __shfl_sync(FULL, U2, (lane + 1) & 31);
        unsigned D2m = __shfl_sync(FULL, D2, (lane + 31) & 31);
        unsigned D2p = __shfl_sync(FULL, D2, (lane + 1) & 31);
        if (ln == 0)  { Cm = 0u; U1m = 0u; D1m = 0u; U2m = 0u; D2m = 0u; }
        if (ln == 15) { Cp = 0u; U1p = 0u; D1p = 0u; U2p = 0u; D2p = 0u; }

        // distance^2 tiers over the 5x5 neighborhood (exact)
        unsigned t0 = C;
        unsigned t1 = sh1(C, Cm, Cp) | U1 | D1;                       // (0,±1),(±1,0)
        unsigned t2 = sh1(U1, U1m, U1p) | sh1(D1, D1m, D1p);         // (±1,±1)
        unsigned t4 = sh2(C, Cm, Cp) | U2 | D2;                       // (0,±2),(±2,0)
        unsigned t5 = sh2(U1, U1m, U1p) | sh2(D1, D1m, D1p)          // (±1,±2)
                    | sh1(U2, U2m, U2p) | sh1(D2, D2m, D2p);         // (±2,±1)
        unsigned t8 = sh2(U2, U2m, U2p) | sh2(D2, D2m, D2p);         // (±2,±2)

        unsigned n1 = t0 | t1;
        unsigned n2 = n1 | t2;
        unsigned n4 = n2 | t4;
        unsigned n5 = n4 | t5;
        unsigned n8 = n5 | t8;

        int v = 0;
        if (G & t1 & ~t0) v = 1;
        if (G & t2 & ~n1) v = 2;
        if (G & t4 & ~n2) v = 4;
        if (G & t5 & ~n4) v = 5;
        if (G & t8 & ~n5) v = 8;

        unsigned leftover = G & ~n8;          // p ~ 2^-25 per gated pixel
        int j0 = ln * 32;
        while (leftover) {
            int bbit = __ffs(leftover) - 1;
            leftover &= leftover - 1u;
            v = max(v, exact_d2(im, row, j0 + bbit));
        }

        #pragma unroll
        for (int o = 16; o > 0; o >>= 1)
            v = max(v, __shfl_down_sync(FULL, v, o));
        if (lane == 0) s_red[w] = v;
        __syncthreads();
        if (t == 0) {
            int m = s_red[0];
            #pragma unroll
            for (int k = 1; k < NW; k++) m = max(m, s_red[k]);
            atomicMax(&g_hmax[blk >> 4], (unsigned)m);
        }
    }

    // ------- completion: block 0 finalizes ----------------------------------
    __syncthreads();
    __shared__ unsigned s_old;
    if (t == 0) {
        __threadfence();
        s_old = atomicAdd(&g_bar2, 1u);
    }
    if (blk != 0) return;
    __syncthreads();
    if (t == 0) {
        unsigned target = (s_old / NBLK + 1u) * NBLK;
        while (*(volatile unsigned int*)&g_bar2 < target) { }
        __threadfence();
    }
    __syncthreads();

    if (t < 32) {
        float term = 0.0f;
        unsigned h2u = 0u;
        int anyA = 0, anyB = 0;
        if (t < NB) {
            h2u = max(g_hmax[t], g_hmax[t + 8]);
            #pragma unroll
            for (int k = 0; k < 16; k++) {
                anyA |= g_anyp[t][k];
                anyB |= g_anyp[t + 8][k];
            }
        }
        __syncwarp();
        if (t < NIMG) g_hmax[t] = 0u;        // reset for next replay
        if (t < NB) {
            bool empty = !(anyA && anyB);
            float hd = sqrtf((float)h2u);
            term = empty ? 1.0f : (1.0f - 1.0f / (1.0f + hd));
        }
        #pragma unroll
        for (int o = 16; o > 0; o >>= 1)
            term += __shfl_down_sync(FULL, term, o);
        if (t == 0) out[0] = term / (float)NB;
    }
}

extern "C" void kernel_launch(void* const* d_in, const int* in_sizes, int n_in,
                              void* d_out, int out_size) {
    const float* inputs  = (const float*)d_in[0];
    const float* targets = (const float*)d_in[1];
    float* out = (float*)d_out;
    hausdorff_fused<<<NBLK, NTHR>>>(inputs, targets, out);
}

// round 8
// speedup vs baseline: 1.1671x; 1.0051x over previous
#include <cuda_runtime.h>
#include <math.h>

#define HH 512
#define WW 512
#define NB 8
#define NIMG 16
#define NBLK 256
#define NTHR 512
#define NW 16            // warps per block
#define PAIRBLK 32       // blocks per image pair (16 for A-image + 16 for B-image)
#define FULL 0xffffffffu

// packed thresholded masks: [image][row][16 words of 32 cols] = 512 KB
__device__ unsigned int g_mbits[NIMG][HH][16];
// per-(image, block-slice) nonempty flags (written unconditionally -> replay safe)
__device__ int g_anyp[NIMG][16];
// running max dt^2 per EDT-image. Reset by finalizer each replay.
__device__ unsigned int g_hmax[NIMG];
// monotonic per-pair barriers + completion counter (grow across replays)
__device__ unsigned int g_pairbar[NB];
__device__ unsigned int g_done = 0;

// nearest set-bit horizontal distance in a 512-bit packed row (clamped 1024)
__device__ __forceinline__ int nearest_dj(const unsigned int* __restrict__ rb, int j) {
    int jw = j >> 5, jb = j & 31;
    unsigned wj = rb[jw];
    int dright = 1 << 20;
    unsigned hi = wj >> jb;
    if (hi) dright = __ffs(hi) - 1;
    else {
        #pragma unroll 4
        for (int w = jw + 1; w < 16; w++) {
            unsigned x = rb[w];
            if (x) { dright = (w << 5) + __ffs(x) - 1 - j; break; }
        }
    }
    int dleft = 1 << 20;
    unsigned lo = jb ? (wj & ((1u << jb) - 1u)) : 0u;
    if (lo) dleft = jb - (31 - __clz(lo));
    else {
        #pragma unroll 4
        for (int w = jw - 1; w >= 0; w--) {
            if ((j - ((w << 5) + 31)) >= dright) break;
            unsigned x = rb[w];
            if (x) { dleft = j - ((w << 5) + 31 - __clz(x)); break; }
        }
    }
    return min(min(dright, dleft), 1024);
}

// exact squared distance for an (astronomically rare) pixel with empty 5x5
__device__ __noinline__ int exact_d2(int im, int row, int j) {
    int best2 = 1 << 19;
    for (int dr = 0; dr < HH; dr++) {
        int dr2 = dr * dr;
        if (dr2 >= best2) break;
        int r = row - dr;
        if (r >= 0) {
            int dj = nearest_dj(g_mbits[im][r], j);
            best2 = min(best2, dr2 + dj * dj);
        }
        if (dr) {
            r = row + dr;
            if (r < HH) {
                int dj = nearest_dj(g_mbits[im][r], j);
                best2 = min(best2, dr2 + dj * dj);
            }
        }
    }
    return best2;
}

// pack 16 threshold bits from 4 float4 loads (frag bit p <-> col lane*16+p)
__device__ __forceinline__ unsigned pack16(const float4* __restrict__ rp4, int lane) {
    float4 a = rp4[lane * 4 + 0];
    float4 b = rp4[lane * 4 + 1];
    float4 c = rp4[lane * 4 + 2];
    float4 d = rp4[lane * 4 + 3];
    unsigned f = 0u;
    f |= (a.x > 0.5f ? 1u : 0u) << 0;  f |= (a.y > 0.5f ? 1u : 0u) << 1;
    f |= (a.z > 0.5f ? 1u : 0u) << 2;  f |= (a.w > 0.5f ? 1u : 0u) << 3;
    f |= (b.x > 0.5f ? 1u : 0u) << 4;  f |= (b.y > 0.5f ? 1u : 0u) << 5;
    f |= (b.z > 0.5f ? 1u : 0u) << 6;  f |= (b.w > 0.5f ? 1u : 0u) << 7;
    f |= (c.x > 0.5f ? 1u : 0u) << 8;  f |= (c.y > 0.5f ? 1u : 0u) << 9;
    f |= (c.z > 0.5f ? 1u : 0u) << 10; f |= (c.w > 0.5f ? 1u : 0u) << 11;
    f |= (d.x > 0.5f ? 1u : 0u) << 12; f |= (d.y > 0.5f ? 1u : 0u) << 13;
    f |= (d.z > 0.5f ? 1u : 0u) << 14; f |= (d.w > 0.5f ? 1u : 0u) << 15;
    return f;
}

__device__ __forceinline__ unsigned sh1(unsigned x, unsigned xm, unsigned xp) {
    return ((x << 1) | (xm >> 31)) | ((x >> 1) | (xp << 31));
}
__device__ __forceinline__ unsigned sh2(unsigned x, unsigned xm, unsigned xp) {
    return ((x << 2) | (xm >> 30)) | ((x >> 2) | (xp << 30));
}

__global__ __launch_bounds__(NTHR, 2)
void hausdorff_fused(const float* __restrict__ inA,
                     const float* __restrict__ inB,
                     float* __restrict__ out) {
    __shared__ int s_red[NW];
    __shared__ unsigned s_old;
    const int t    = threadIdx.x;
    const int w    = t >> 5;
    const int lane = t & 31;
    const int blk  = blockIdx.x;
    const int gw   = blk * NW + w;        // 0..4095
    const int im   = gw >> 8;             // 256 warp-units per image
    const int pair = gw & 255;
    const int row0 = pair * 2;
    const int pr   = im & 7;              // image pair id (0..7)

    // ------- Phase 1: threshold + bit-pack ----------------------------------
    {
        const int b = im & 7;
        const float* src = ((im < NB) ? inA : inB) + (size_t)b * HH * WW;
        unsigned f0 = pack16((const float4*)(src + (size_t)row0 * WW), lane);
        unsigned f1 = pack16((const float4*)(src + (size_t)(row0 + 1) * WW), lane);

        int widx = (lane & 15) * 2;
        unsigned w0 = __shfl_sync(FULL, f0, widx) | (__shfl_sync(FULL, f0, widx + 1) << 16);
        unsigned w1 = __shfl_sync(FULL, f1, widx) | (__shfl_sync(FULL, f1, widx + 1) << 16);
        if (lane < 16) {
            g_mbits[im][row0][lane]     = w0;
            g_mbits[im][row0 + 1][lane] = w1;
        }
        int anyb = __syncthreads_or((f0 | f1) != 0u);
        if (t == 0) g_anyp[blk >> 4][blk & 15] = anyb;
    }

    // ------- per-pair barrier (32 blocks: both images of this pair) ---------
    {
        if (t == 0) {
            __threadfence();
            unsigned old = atomicAdd(&g_pairbar[pr], 1u);
            unsigned target = (old / PAIRBLK + 1u) * PAIRBLK;
            while (*(volatile unsigned int*)&g_pairbar[pr] < target) { }
            __threadfence();
        }
        __syncthreads();
    }

    // ------- Phase 2: 5x5 tiered exact Hausdorff max ------------------------
    {
        const int half = lane >> 4;
        const int ln   = lane & 15;
        const int row  = row0 + half;
        const int oim  = im ^ 8;

        unsigned C  = g_mbits[im][row][ln];
        unsigned U1 = (row > 0)      ? g_mbits[im][row - 1][ln] : 0u;
        unsigned D1 = (row < HH - 1) ? g_mbits[im][row + 1][ln] : 0u;
        unsigned U2 = (row > 1)      ? g_mbits[im][row - 2][ln] : 0u;
        unsigned D2 = (row < HH - 2) ? g_mbits[im][row + 2][ln] : 0u;
        unsigned G  = g_mbits[oim][row][ln];

        unsigned Cm  = __shfl_sync(FULL, C,  (lane + 31) & 31);
        unsigned Cp  = __shfl_sync(FULL, C,  (lane + 1) & 31);
        unsigned U1m = __shfl_sync(FULL, U1, (lane + 31) & 31);
        unsigned U1p = __shfl_sync(FULL, U1, (lane + 1) & 31);
        unsigned D1m = __shfl_sync(FULL, D1, (lane + 31) & 31);
        unsigned D1p = __shfl_sync(FULL, D1, (lane + 1) & 31);
        unsigned U2m = __shfl_sync(FULL, U2, (lane + 31) & 31);
        unsigned U2p = __shfl_sync(FULL, U2, (lane + 1) & 31);
        unsigned D2m = __shfl_sync(FULL, D2, (lane + 31) & 31);
        unsigned D2p = __shfl_sync(FULL, D2, (lane + 1) & 31);
        if (ln == 0)  { Cm = 0u; U1m = 0u; D1m = 0u; U2m = 0u; D2m = 0u; }
        if (ln == 15) { Cp = 0u; U1p = 0u; D1p = 0u; U2p = 0u; D2p = 0u; }

        unsigned t0 = C;
        unsigned t1 = sh1(C, Cm, Cp) | U1 | D1;
        unsigned t2 = sh1(U1, U1m, U1p) | sh1(D1, D1m, D1p);
        unsigned t4 = sh2(C, Cm, Cp) | U2 | D2;
        unsigned t5 = sh2(U1, U1m, U1p) | sh2(D1, D1m, D1p)
                    | sh1(U2, U2m, U2p) | sh1(D2, D2m, D2p);
        unsigned t8 = sh2(U2, U2m, U2p) | sh2(D2, D2m, D2p);

        unsigned n1 = t0 | t1;
        unsigned n2 = n1 | t2;
        unsigned n4 = n2 | t4;
        unsigned n5 = n4 | t5;
        unsigned n8 = n5 | t8;

        int v = 0;
        if (G & t1 & ~t0) v = 1;
        if (G & t2 & ~n1) v = 2;
        if (G & t4 & ~n2) v = 4;
        if (G & t5 & ~n4) v = 5;
        if (G & t8 & ~n5) v = 8;

        unsigned leftover = G & ~n8;          // p ~ 2^-25 per gated pixel
        int j0 = ln * 32;
        while (leftover) {
            int bbit = __ffs(leftover) - 1;
            leftover &= leftover - 1u;
            v = max(v, exact_d2(im, row, j0 + bbit));
        }

        #pragma unroll
        for (int o = 16; o > 0; o >>= 1)
            v = max(v, __shfl_down_sync(FULL, v, o));
        if (lane == 0) s_red[w] = v;
        __syncthreads();
        if (t == 0) {
            int m = s_red[0];
            #pragma unroll
            for (int k = 1; k < NW; k++) m = max(m, s_red[k]);
            atomicMax(&g_hmax[blk >> 4], (unsigned)m);
        }
    }

    // ------- completion: LAST-arriving block finalizes ----------------------
    __syncthreads();
    if (t == 0) {
        __threadfence();
        s_old = atomicAdd(&g_done, 1u);
    }
    __syncthreads();
    if (((s_old + 1u) % NBLK) != 0u) return;   // exactly one block per replay

    if (t < 32) {
        float term = 0.0f;
        unsigned h2u = 0u;
        int anyA = 0, anyB = 0;
        if (t < NB) {
            h2u = max(g_hmax[t], g_hmax[t + 8]);
            #pragma unroll
            for (int k = 0; k < 16; k++) {
                anyA |= g_anyp[t][k];
                anyB |= g_anyp[t + 8][k];
            }
        }
        __syncwarp();
        if (t < NIMG) g_hmax[t] = 0u;        // reset for next replay
        if (t < NB) {
            bool empty = !(anyA && anyB);
            float hd = sqrtf((float)h2u);
            term = empty ? 1.0f : (1.0f - 1.0f / (1.0f + hd));
        }
        #pragma unroll
        for (int o = 16; o > 0; o >>= 1)
            term += __shfl_down_sync(FULL, term, o);
        if (t == 0) out[0] = term / (float)NB;
    }
}

extern "C" void kernel_launch(void* const* d_in, const int* in_sizes, int n_in,
                              void* d_out, int out_size) {
    const float* inputs  = (const float*)d_in[0];
    const float* targets = (const float*)d_in[1];
    float* out = (float*)d_out;
    hausdorff_fused<<<NBLK, NTHR>>>(inputs, targets, out);
}